// round 3
// baseline (speedup 1.0000x reference)
#include <cuda_runtime.h>
#include <math.h>

#define NB   4
#define NCLS 3
#define FH   256       // feature H=W
#define CH   128       // coarse H=W
#define NIN  128
#define KIN  131
#define FCK  132       // KIN padded to 11*12
#define KCH  12        // k-chunk
#define NCH  11
#define PPB  8192
#define PTOT 32768
#define KEYSTRIDE 262144
#define TOPK 8192u

// ---------------- scratch ----------------
__device__ float        g_featT[(size_t)NB*FH*FH*NIN];   // NHWC features
__device__ float        g_sem256[NB*NCLS*256*256];
__device__ unsigned int g_keys[NB*KEYSTRIDE];
__device__ unsigned int g_hist2[NB*4096];
__device__ unsigned long long g_cand[(size_t)NB*KEYSTRIDE];
__device__ int          g_idx[PTOT];
__device__ float        g_Xa[(size_t)FCK*PTOT];
__device__ float        g_Xb[(size_t)FCK*PTOT];
__device__ float2       g_Wd[(size_t)3*FCK*NIN];         // dup-packed transposed weights

__device__ __forceinline__ unsigned int fkey(float f) {
    unsigned int u = __float_as_uint(f);
    return (u & 0x80000000u) ? ~u : (u | 0x80000000u);
}
__device__ __forceinline__ unsigned long long ffma2(unsigned long long a, unsigned long long b, unsigned long long c) {
    unsigned long long d;
    asm("fma.rn.f32x2 %0, %1, %2, %3;" : "=l"(d) : "l"(a), "l"(b), "l"(c));
    return d;
}
__device__ __forceinline__ void unpack2(unsigned long long v, float& lo, float& hi) {
    unsigned int a, b;
    asm("mov.b64 {%0,%1}, %2;" : "=r"(a), "=r"(b) : "l"(v));
    lo = __uint_as_float(a); hi = __uint_as_float(b);
}

// ---------------- one-time prep: pads, histograms, weight pack ----------------
__global__ void prep_kernel(const float* __restrict__ w1, const float* __restrict__ w2,
                            const float* __restrict__ w3) {
    int i = blockIdx.x*blockDim.x + threadIdx.x;
    int stride = gridDim.x*blockDim.x;
    for (int j = i; j < PTOT; j += stride) {
        g_Xa[(size_t)(FCK-1)*PTOT + j] = 0.f;
        g_Xb[(size_t)(FCK-1)*PTOT + j] = 0.f;
    }
    for (int j = i; j < NB*4096; j += stride) g_hist2[j] = 0;
    for (int j = i; j < 3*FCK*NIN; j += stride) {
        int l = j / (FCK*NIN); int r = j - l*(FCK*NIN);
        int k = r >> 7; int o = r & 127;
        const float* w = (l == 0) ? w1 : ((l == 1) ? w2 : w3);
        float v = (k < KIN) ? w[o*KIN + k] : 0.f;
        g_Wd[j] = make_float2(v, v);
    }
}

// ---------------- features NCHW -> NHWC ----------------
__global__ void transpose_kernel(const float* __restrict__ f) {
    __shared__ float tile[32][33];
    int n = blockIdx.z;
    int pix0 = blockIdx.x * 32;
    int c0   = blockIdx.y * 32;
    int tx = threadIdx.x, ty = threadIdx.y;
    #pragma unroll
    for (int i = ty; i < 32; i += 8)
        tile[i][tx] = f[(size_t)(n*NIN + c0 + i)*(FH*FH) + pix0 + tx];
    __syncthreads();
    #pragma unroll
    for (int i = ty; i < 32; i += 8)
        g_featT[(size_t)(n*(FH*FH) + pix0 + i)*NIN + c0 + tx] = tile[tx][i];
}

// ---------------- fused 2x upsample + uncertainty key + 4096-bin histogram ----------------
__global__ void upsample_unc_hist(const float* __restrict__ in, float* __restrict__ out, int logW) {
    __shared__ unsigned int sh[4096];
    int n = blockIdx.y;
    for (int i = threadIdx.x; i < 4096; i += blockDim.x) sh[i] = 0;
    __syncthreads();
    int W = 1 << logW, Hin = W >> 1;
    int HW = W << logW;
    for (int pix = blockIdx.x*blockDim.x + threadIdx.x; pix < HW; pix += gridDim.x*blockDim.x) {
        int y = pix >> logW;  int x = pix & (W - 1);
        int y0 = (y - 1) >> 1, x0 = (x - 1) >> 1;
        float wy1 = (y & 1) ? 0.25f : 0.75f;
        float wx1 = (x & 1) ? 0.25f : 0.75f;
        int y1 = y0 + 1, x1 = x0 + 1;
        int xa = (x0 < 0) ? 0 : x0;
        int xb = (x1 > Hin-1) ? Hin-1 : x1;
        float v[NCLS];
        #pragma unroll
        for (int c = 0; c < NCLS; c++) {
            const float* p = in + (size_t)(n*NCLS + c)*Hin*Hin;
            float colA, colB;
            if (y0 < 0)            { colA = p[xa];               colB = p[xb]; }
            else if (y1 > Hin - 1) { colA = p[(Hin-1)*Hin + xa]; colB = p[(Hin-1)*Hin + xb]; }
            else {
                colA = (1.f - wy1)*p[y0*Hin + xa] + wy1*p[y1*Hin + xa];
                colB = (1.f - wy1)*p[y0*Hin + xb] + wy1*p[y1*Hin + xb];
            }
            float vv;
            if (x0 < 0)            vv = colA;
            else if (x1 > Hin - 1) vv = colB;
            else                   vv = (1.f - wx1)*colA + wx1*colB;
            v[c] = vv;
            out[(size_t)(n*NCLS + c)*HW + pix] = vv;
        }
        float hi = fmaxf(v[0], v[1]), lo = fminf(v[0], v[1]);
        float m1 = fmaxf(hi, v[2]);
        float m2 = fmaxf(lo, fminf(hi, v[2]));
        unsigned int key = fkey(m2 - m1);
        g_keys[n*KEYSTRIDE + pix] = key;
        atomicAdd(&sh[key >> 20], 1u);
    }
    __syncthreads();
    for (int i = threadIdx.x; i < 4096; i += blockDim.x) {
        unsigned int v = sh[i];
        if (v) atomicAdd(&g_hist2[n*4096 + i], v);
    }
}

// ---------------- fused resolve + compact + exact candidate select (1 block/batch) ----------------
__global__ void finalize_kernel(int HW) {
    int n = blockIdx.x, t = threadIdx.x;   // 1024 threads
    __shared__ unsigned int s[1024];
    __shared__ unsigned int hist[2048];
    __shared__ int sh_bstar, sh_kRem, selCount, candCount, sh_d;
    __shared__ unsigned int sh_sub;
    unsigned int* gh = g_hist2 + n*4096;
    int base = 4095 - 4*t;                  // descending bins
    unsigned int h0 = gh[base], h1 = gh[base-1], h2 = gh[base-2], h3 = gh[base-3];
    unsigned int sum = h0 + h1 + h2 + h3;
    s[t] = sum;
    __syncthreads();
    for (int off = 1; off < 1024; off <<= 1) {
        unsigned int v = (t >= off) ? s[t - off] : 0u;
        __syncthreads();
        s[t] += v;
        __syncthreads();
    }
    unsigned int incl = s[t], excl = incl - sum;
    if (excl < TOPK && TOPK <= incl) {
        unsigned int c = excl;
        if (c + h0 >= TOPK)      { sh_bstar = base;     sh_kRem = (int)(TOPK - c); }
        else { c += h0;
        if (c + h1 >= TOPK)      { sh_bstar = base - 1; sh_kRem = (int)(TOPK - c); }
        else { c += h1;
        if (c + h2 >= TOPK)      { sh_bstar = base - 2; sh_kRem = (int)(TOPK - c); }
        else { c += h2;            sh_bstar = base - 3; sh_kRem = (int)(TOPK - c); } } }
    }
    gh[t] = 0; gh[t+1024] = 0; gh[t+2048] = 0; gh[t+3072] = 0;   // clean for next step
    if (t == 0) { selCount = 0; candCount = 0; }
    __syncthreads();
    int bstar = sh_bstar;
    int need  = sh_kRem;
    const unsigned int* keys = g_keys + n*KEYSTRIDE;
    unsigned long long* cand = g_cand + (size_t)n*KEYSTRIDE;
    for (int i = t; i < HW; i += 1024) {
        unsigned int key = keys[i];
        int b = (int)(key >> 20);
        if (b > bstar) {
            int p = atomicAdd(&selCount, 1);
            g_idx[n*PPB + p] = i;
        } else if (b == bstar) {
            int p = atomicAdd(&candCount, 1);
            cand[p] = ((unsigned long long)key << 32) | (unsigned int)(~(unsigned int)i);
        }
    }
    __syncthreads();
    int m = candCount;
    unsigned long long prefix = 0, pmask = 0;
    if (m > need) {
        const int shifts[6] = {53, 42, 31, 20, 9, 0};
        for (int pass = 0; pass < 6; pass++) {
            int shift = shifts[pass];
            for (int i = t; i < 2048; i += 1024) hist[i] = 0;
            __syncthreads();
            for (int i = t; i < m; i += 1024) {
                unsigned long long c = cand[i];
                if ((c & pmask) == prefix)
                    atomicAdd(&hist[(unsigned int)(c >> shift) & 0x7FFu], 1u);
            }
            __syncthreads();
            unsigned int a = hist[2047 - 2*t], b = hist[2046 - 2*t];
            s[t] = a + b;
            __syncthreads();
            for (int off = 1; off < 1024; off <<= 1) {
                unsigned int v = (t >= off) ? s[t - off] : 0u;
                __syncthreads();
                s[t] += v;
                __syncthreads();
            }
            unsigned int incl2 = s[t], excl2 = incl2 - (a + b);
            unsigned int un = (unsigned int)need;
            if (excl2 < un && un <= incl2) {
                if (excl2 + a >= un) { sh_d = 2047 - 2*t; sh_sub = excl2; }
                else                 { sh_d = 2046 - 2*t; sh_sub = excl2 + a; }
            }
            __syncthreads();
            need -= (int)sh_sub;
            prefix |= ((unsigned long long)(unsigned int)sh_d) << shift;
            pmask  |= 0x7FFull << shift;
            __syncthreads();
        }
    }
    for (int i = t; i < m; i += 1024) {
        unsigned long long c = cand[i];
        if (c >= prefix) {
            int p = atomicAdd(&selCount, 1);
            g_idx[n*PPB + p] = (int)(~(unsigned int)(c & 0xFFFFFFFFull));
        }
    }
}

// ---------------- gather: warp-per-point float4 bilinear sample -> X [131][PTOT] ----------------
__global__ void gather_kernel(const float* __restrict__ coarse, int logW) {
    __shared__ float tile[136][33];       // [ch][pt]
    __shared__ int   sx0[32], sy0[32];
    __shared__ float sw0[32], sw1[32], sw2[32], sw3[32];
    __shared__ float spx[32], spy[32];
    int pBase = blockIdx.x * 32;
    int tid = threadIdx.x;                // 256
    int lane = tid & 31, wrp = tid >> 5;  // 8 warps
    int n = pBase >> 13;
    if (tid < 32) {
        int id = g_idx[pBase + tid];
        int W = 1 << logW;
        float inv = 1.f / (float)W;
        float px = ((float)(id & (W-1)) + 0.5f) * inv;
        float py = ((float)(id >> logW) + 0.5f) * inv;
        spx[tid] = px; spy[tid] = py;
        float fx = px * 256.f - 0.5f, fy = py * 256.f - 0.5f;
        float fx0 = floorf(fx), fy0 = floorf(fy);
        float wx1 = fx - fx0, wy1 = fy - fy0;
        sx0[tid] = (int)fx0; sy0[tid] = (int)fy0;
        sw0[tid] = (1.f-wx1)*(1.f-wy1);
        sw1[tid] = wx1*(1.f-wy1);
        sw2[tid] = (1.f-wx1)*wy1;
        sw3[tid] = wx1*wy1;
    }
    __syncthreads();
    const float* base = g_featT + (size_t)n*FH*FH*NIN;
    int off = lane << 2;   // 4 channels per lane
    #pragma unroll
    for (int it = 0; it < 4; it++) {
        int j = wrp + it*8;
        int x0 = sx0[j], y0 = sy0[j];
        bool xv0 = (x0 >= 0), xv1 = (x0+1 < FH), yv0 = (y0 >= 0), yv1 = (y0+1 < FH);
        float a0 = 0.f, a1 = 0.f, a2 = 0.f, a3 = 0.f;
        if (xv0 && yv0) { float w = sw0[j]; float4 v = *(const float4*)(base + (size_t)((y0  )*FH + x0  )*NIN + off);
                          a0 += w*v.x; a1 += w*v.y; a2 += w*v.z; a3 += w*v.w; }
        if (xv1 && yv0) { float w = sw1[j]; float4 v = *(const float4*)(base + (size_t)((y0  )*FH + x0+1)*NIN + off);
                          a0 += w*v.x; a1 += w*v.y; a2 += w*v.z; a3 += w*v.w; }
        if (xv0 && yv1) { float w = sw2[j]; float4 v = *(const float4*)(base + (size_t)((y0+1)*FH + x0  )*NIN + off);
                          a0 += w*v.x; a1 += w*v.y; a2 += w*v.z; a3 += w*v.w; }
        if (xv1 && yv1) { float w = sw3[j]; float4 v = *(const float4*)(base + (size_t)((y0+1)*FH + x0+1)*NIN + off);
                          a0 += w*v.x; a1 += w*v.y; a2 += w*v.z; a3 += w*v.w; }
        tile[off+0][j] = a0; tile[off+1][j] = a1; tile[off+2][j] = a2; tile[off+3][j] = a3;
    }
    if (tid < 96) {
        int j = tid / 3, cc = tid - (tid/3)*3;
        float cx = spx[j]*128.f - 0.5f, cy = spy[j]*128.f - 0.5f;
        float cx0f = floorf(cx), cy0f = floorf(cy);
        int x0 = (int)cx0f, y0 = (int)cy0f;
        float wx1 = cx - cx0f, wy1 = cy - cy0f;
        const float* p = coarse + (size_t)(n*NCLS + cc)*CH*CH;
        float acc = 0.f;
        if (x0 >= 0   && y0 >= 0  ) acc += (1.f-wx1)*(1.f-wy1)*p[y0*CH + x0];
        if (x0+1 < CH && y0 >= 0  ) acc += wx1*(1.f-wy1)*p[y0*CH + x0+1];
        if (x0 >= 0   && y0+1 < CH) acc += (1.f-wx1)*wy1*p[(y0+1)*CH + x0];
        if (x0+1 < CH && y0+1 < CH) acc += wx1*wy1*p[(y0+1)*CH + x0+1];
        tile[NIN + cc][j] = acc;
    }
    __syncthreads();
    for (int idx = tid; idx < KIN*32; idx += 256) {
        int r = idx >> 5, j = idx & 31;
        float vv = tile[r][j];
        g_Xa[(size_t)r*PTOT + pBase + j] = vv;
        if (r >= NIN) g_Xb[(size_t)r*PTOT + pBase + j] = vv;
    }
}

// ---------------- FC layer (f32x2); last layer fuses head (131->3) + scatter ----------------
__global__ void __launch_bounds__(256, 2)
fc_kernel(const float* __restrict__ X, float* __restrict__ Y,
          const float2* __restrict__ Wd, const float* __restrict__ B,
          int last, const float* __restrict__ wph, const float* __restrict__ bph,
          float* __restrict__ sem, int HW) {
    extern __shared__ float sm[];
    float2* Wb = (float2*)sm;          // [2][KCH*128] float2  (24,576 B)
    float*  Xb = sm + 6144;            // [2][KCH*128] float   (12,288 B)
    int tid = threadIdx.x;
    int pBase = blockIdx.x * 128;

    // stage chunk 0
    {
        const float4* wg = (const float4*)Wd;
        float4* wd = (float4*)Wb;
        wd[tid] = wg[tid]; wd[tid+256] = wg[tid+256]; wd[tid+512] = wg[tid+512];
        float4* xd = (float4*)Xb;
        { int f = tid;      int kk = f >> 5, c4 = f & 31; xd[f] = *(const float4*)(X + (size_t)kk*PTOT + pBase + (c4 << 2)); }
        if (tid < 128) { int f = tid+256; int kk = f >> 5, c4 = f & 31; xd[f] = *(const float4*)(X + (size_t)kk*PTOT + pBase + (c4 << 2)); }
    }
    __syncthreads();

    int o0 = (tid >> 4) << 3;
    int p0 = (tid & 15) << 3;
    unsigned long long acc[8][4];
    #pragma unroll
    for (int o = 0; o < 8; o++)
        #pragma unroll
        for (int j = 0; j < 4; j++) acc[o][j] = 0ull;

    float4 wpre[3], xpre[2];
    for (int cch = 0; cch < NCH; cch++) {
        int cur = cch & 1;
        if (cch < NCH-1) {
            const float4* wg = (const float4*)(Wd + (size_t)(cch+1)*(KCH*NIN));
            wpre[0] = wg[tid]; wpre[1] = wg[tid+256]; wpre[2] = wg[tid+512];
            const float* Xn = X + (size_t)(cch+1)*KCH*PTOT;
            { int f = tid;      int kk = f >> 5, c4 = f & 31; xpre[0] = *(const float4*)(Xn + (size_t)kk*PTOT + pBase + (c4 << 2)); }
            if (tid < 128) { int f = tid+256; int kk = f >> 5, c4 = f & 31; xpre[1] = *(const float4*)(Xn + (size_t)kk*PTOT + pBase + (c4 << 2)); }
        }
        float2* Wc = Wb + cur*(KCH*NIN);
        float*  Xc = Xb + cur*(KCH*NIN);
        #pragma unroll
        for (int kk = 0; kk < KCH; kk++) {
            const ulonglong2* wrow = (const ulonglong2*)(Wc + kk*128 + o0);
            const ulonglong2* xrow = (const ulonglong2*)(Xc + kk*128 + p0);
            ulonglong2 w01 = wrow[0], w23 = wrow[1], w45 = wrow[2], w67 = wrow[3];
            ulonglong2 xA = xrow[0], xB = xrow[1];
            unsigned long long w[8] = {w01.x, w01.y, w23.x, w23.y, w45.x, w45.y, w67.x, w67.y};
            unsigned long long x[4] = {xA.x, xA.y, xB.x, xB.y};
            #pragma unroll
            for (int o = 0; o < 8; o++)
                #pragma unroll
                for (int j = 0; j < 4; j++)
                    acc[o][j] = ffma2(w[o], x[j], acc[o][j]);
        }
        if (cch < NCH-1) {
            __syncthreads();
            int nb = cur ^ 1;
            float4* wd = (float4*)(Wb + nb*(KCH*NIN));
            wd[tid] = wpre[0]; wd[tid+256] = wpre[1]; wd[tid+512] = wpre[2];
            float4* xd = (float4*)(Xb + nb*(KCH*NIN));
            xd[tid] = xpre[0];
            if (tid < 128) xd[tid+256] = xpre[1];
            __syncthreads();
        }
    }

    if (!last) {
        #pragma unroll
        for (int o = 0; o < 8; o++) {
            float bo = __ldg(&B[o0 + o]);
            float r[8];
            #pragma unroll
            for (int j = 0; j < 4; j++) unpack2(acc[o][j], r[2*j], r[2*j+1]);
            float4 outA, outB;
            outA.x = fmaxf(r[0]+bo, 0.f); outA.y = fmaxf(r[1]+bo, 0.f);
            outA.z = fmaxf(r[2]+bo, 0.f); outA.w = fmaxf(r[3]+bo, 0.f);
            outB.x = fmaxf(r[4]+bo, 0.f); outB.y = fmaxf(r[5]+bo, 0.f);
            outB.z = fmaxf(r[6]+bo, 0.f); outB.w = fmaxf(r[7]+bo, 0.f);
            *(float4*)(Y + (size_t)(o0+o)*PTOT + pBase + p0)     = outA;
            *(float4*)(Y + (size_t)(o0+o)*PTOT + pBase + p0 + 4) = outB;
        }
    } else {
        // fused head: relu outs -> smem [pt][133], then 3x131 dot + scatter
        __syncthreads();
        #pragma unroll
        for (int o = 0; o < 8; o++) {
            float bo = __ldg(&B[o0 + o]);
            float r[8];
            #pragma unroll
            for (int j = 0; j < 4; j++) unpack2(acc[o][j], r[2*j], r[2*j+1]);
            #pragma unroll
            for (int p = 0; p < 8; p++)
                sm[(p0+p)*133 + (o0+o)] = fmaxf(r[p] + bo, 0.f);
        }
        __syncthreads();
        if (tid < 128) {
            int gp = pBase + tid;
            float c0 = X[(size_t)128*PTOT + gp];
            float c1 = X[(size_t)129*PTOT + gp];
            float c2 = X[(size_t)130*PTOT + gp];
            const float* row = sm + tid*133;
            float a0 = 0.f, a1 = 0.f, a2 = 0.f;
            for (int k = 0; k < NIN; k++) {
                float xv = row[k];
                a0 += __ldg(&wph[k])*xv;
                a1 += __ldg(&wph[KIN + k])*xv;
                a2 += __ldg(&wph[2*KIN + k])*xv;
            }
            a0 += __ldg(&wph[128])*c0;       a0 += __ldg(&wph[129])*c1;       a0 += __ldg(&wph[130])*c2;
            a1 += __ldg(&wph[KIN+128])*c0;   a1 += __ldg(&wph[KIN+129])*c1;   a1 += __ldg(&wph[KIN+130])*c2;
            a2 += __ldg(&wph[2*KIN+128])*c0; a2 += __ldg(&wph[2*KIN+129])*c1; a2 += __ldg(&wph[2*KIN+130])*c2;
            int nn = gp >> 13;
            int id = g_idx[gp];
            sem[(size_t)(nn*NCLS + 0)*HW + id] = a0 + __ldg(&bph[0]);
            sem[(size_t)(nn*NCLS + 1)*HW + id] = a1 + __ldg(&bph[1]);
            sem[(size_t)(nn*NCLS + 2)*HW + id] = a2 + __ldg(&bph[2]);
        }
    }
}

// ---------------- launch ----------------
extern "C" void kernel_launch(void* const* d_in, const int* in_sizes, int n_in,
                              void* d_out, int out_size) {
    const float* coarse = (const float*)d_in[0];
    const float* feat   = (const float*)d_in[1];
    const float* w1 = (const float*)d_in[2];
    const float* b1 = (const float*)d_in[3];
    const float* w2 = (const float*)d_in[4];
    const float* b2 = (const float*)d_in[5];
    const float* w3 = (const float*)d_in[6];
    const float* b3 = (const float*)d_in[7];
    const float* wp = (const float*)d_in[8];
    const float* bp = (const float*)d_in[9];
    float* out = (float*)d_out;

    float *sem256, *Xa, *Xb;
    float2* Wd;
    cudaGetSymbolAddress((void**)&sem256, g_sem256);
    cudaGetSymbolAddress((void**)&Xa, g_Xa);
    cudaGetSymbolAddress((void**)&Xb, g_Xb);
    cudaGetSymbolAddress((void**)&Wd, g_Wd);

    const int FCSMEM = 128*133*4;    // 68,096 B (union: staging 36,864 / head outs)
    cudaFuncSetAttribute(fc_kernel, cudaFuncAttributeMaxDynamicSharedMemorySize, FCSMEM);

    prep_kernel<<<256, 256>>>(w1, w2, w3);
    transpose_kernel<<<dim3(2048, 4, 4), dim3(32, 8)>>>(feat);

    for (int step = 0; step < 2; step++) {
        int logW = (step == 0) ? 8 : 9;
        int HW   = 1 << (2*logW);
        const float* semIn = (step == 0) ? coarse : sem256;
        float* semOut      = (step == 0) ? sem256 : out;

        upsample_unc_hist<<<dim3(HW/1024, NB), 256>>>(semIn, semOut, logW);
        finalize_kernel<<<NB, 1024>>>(HW);
        gather_kernel<<<PTOT/32, 256>>>(coarse, logW);

        fc_kernel<<<PTOT/128, 256, FCSMEM>>>(Xa, Xb, Wd,             b1, 0, 0, 0, 0, 0);
        fc_kernel<<<PTOT/128, 256, FCSMEM>>>(Xb, Xa, Wd + FCK*NIN,   b2, 0, 0, 0, 0, 0);
        fc_kernel<<<PTOT/128, 256, FCSMEM>>>(Xa, 0,  Wd + 2*FCK*NIN, b3, 1, wp, bp, semOut, HW);
    }
}

// round 4
// speedup vs baseline: 1.3375x; 1.3375x over previous
#include <cuda_runtime.h>
#include <math.h>

#define NB   4
#define NCLS 3
#define FH   256       // feature H=W
#define CH   128       // coarse H=W
#define NIN  128
#define KIN  131
#define FCK  132       // KIN padded to 11*12
#define KCH  12
#define NCH  11
#define PPB  8192
#define PTOT 32768
#define KEYSTRIDE 262144
#define TOPK 8192u
#define XS_STRIDE 132
#define WCHUNK 1536    // float2 per chunk (12*128)

// ---------------- scratch ----------------
__device__ float        g_featT[(size_t)NB*FH*FH*NIN];   // NHWC features
__device__ float        g_sem256[NB*NCLS*256*256];
__device__ unsigned int g_keys[NB*KEYSTRIDE];
__device__ unsigned int g_hist2[NB*4096];
__device__ unsigned long long g_cand[(size_t)NB*KEYSTRIDE];
__device__ int          g_bstar[NB];
__device__ int          g_kRem[NB];
__device__ int          g_selCount[NB];
__device__ int          g_candCount[NB];
__device__ int          g_idx[PTOT];
__device__ float2       g_Wd[(size_t)3*FCK*NIN];         // dup-packed weights, chunk-contiguous

__device__ __forceinline__ unsigned int fkey(float f) {
    unsigned int u = __float_as_uint(f);
    return (u & 0x80000000u) ? ~u : (u | 0x80000000u);
}
__device__ __forceinline__ unsigned long long ffma2(unsigned long long a, unsigned long long b, unsigned long long c) {
    unsigned long long d;
    asm("fma.rn.f32x2 %0, %1, %2, %3;" : "=l"(d) : "l"(a), "l"(b), "l"(c));
    return d;
}
__device__ __forceinline__ void unpack2(unsigned long long v, float& lo, float& hi) {
    unsigned int a, b;
    asm("mov.b64 {%0,%1}, %2;" : "=r"(a), "=r"(b) : "l"(v));
    lo = __uint_as_float(a); hi = __uint_as_float(b);
}

// ---------------- one-time prep: histograms + weight pack ----------------
__global__ void prep_kernel(const float* __restrict__ w1, const float* __restrict__ w2,
                            const float* __restrict__ w3) {
    int i = blockIdx.x*blockDim.x + threadIdx.x;
    int stride = gridDim.x*blockDim.x;
    for (int j = i; j < NB*4096; j += stride) g_hist2[j] = 0;
    for (int j = i; j < 3*FCK*NIN; j += stride) {
        int l = j / (FCK*NIN); int r = j - l*(FCK*NIN);
        int k = r >> 7; int o = r & 127;
        const float* w = (l == 0) ? w1 : ((l == 1) ? w2 : w3);
        float v = (k < KIN) ? w[o*KIN + k] : 0.f;
        g_Wd[j] = make_float2(v, v);
    }
}

// ---------------- features NCHW -> NHWC ----------------
__global__ void transpose_kernel(const float* __restrict__ f) {
    __shared__ float tile[32][33];
    int n = blockIdx.z;
    int pix0 = blockIdx.x * 32;
    int c0   = blockIdx.y * 32;
    int tx = threadIdx.x, ty = threadIdx.y;
    #pragma unroll
    for (int i = ty; i < 32; i += 8)
        tile[i][tx] = f[(size_t)(n*NIN + c0 + i)*(FH*FH) + pix0 + tx];
    __syncthreads();
    #pragma unroll
    for (int i = ty; i < 32; i += 8)
        g_featT[(size_t)(n*(FH*FH) + pix0 + i)*NIN + c0 + tx] = tile[tx][i];
}

// ---------------- fused 2x upsample + uncertainty key + 4096-bin histogram ----------------
__global__ void upsample_unc_hist(const float* __restrict__ in, float* __restrict__ out, int logW) {
    __shared__ unsigned int sh[4096];
    int n = blockIdx.y;
    for (int i = threadIdx.x; i < 4096; i += blockDim.x) sh[i] = 0;
    __syncthreads();
    int W = 1 << logW, Hin = W >> 1;
    int HW = W << logW;
    for (int pix = blockIdx.x*blockDim.x + threadIdx.x; pix < HW; pix += gridDim.x*blockDim.x) {
        int y = pix >> logW;  int x = pix & (W - 1);
        int y0 = (y - 1) >> 1, x0 = (x - 1) >> 1;
        float wy1 = (y & 1) ? 0.25f : 0.75f;
        float wx1 = (x & 1) ? 0.25f : 0.75f;
        int y1 = y0 + 1, x1 = x0 + 1;
        int xa = (x0 < 0) ? 0 : x0;
        int xb = (x1 > Hin-1) ? Hin-1 : x1;
        float v[NCLS];
        #pragma unroll
        for (int c = 0; c < NCLS; c++) {
            const float* p = in + (size_t)(n*NCLS + c)*Hin*Hin;
            float colA, colB;
            if (y0 < 0)            { colA = p[xa];               colB = p[xb]; }
            else if (y1 > Hin - 1) { colA = p[(Hin-1)*Hin + xa]; colB = p[(Hin-1)*Hin + xb]; }
            else {
                colA = (1.f - wy1)*p[y0*Hin + xa] + wy1*p[y1*Hin + xa];
                colB = (1.f - wy1)*p[y0*Hin + xb] + wy1*p[y1*Hin + xb];
            }
            float vv;
            if (x0 < 0)            vv = colA;
            else if (x1 > Hin - 1) vv = colB;
            else                   vv = (1.f - wx1)*colA + wx1*colB;
            v[c] = vv;
            out[(size_t)(n*NCLS + c)*HW + pix] = vv;
        }
        float hi = fmaxf(v[0], v[1]), lo = fminf(v[0], v[1]);
        float m1 = fmaxf(hi, v[2]);
        float m2 = fmaxf(lo, fminf(hi, v[2]));
        unsigned int key = fkey(m2 - m1);
        g_keys[n*KEYSTRIDE + pix] = key;
        atomicAdd(&sh[key >> 20], 1u);
    }
    __syncthreads();
    for (int i = threadIdx.x; i < 4096; i += blockDim.x) {
        unsigned int v = sh[i];
        if (v) atomicAdd(&g_hist2[n*4096 + i], v);
    }
}

// ---------------- resolve threshold bucket (NB blocks, 1024 thr, shuffle scan) ----------------
__global__ void resolve_kernel() {
    int n = blockIdx.x, t = threadIdx.x;
    int lane = t & 31, wrp = t >> 5;
    __shared__ unsigned int wsum[32];
    unsigned int* gh = g_hist2 + n*4096;
    int base = 4095 - 4*t;
    unsigned int h0 = gh[base], h1 = gh[base-1], h2 = gh[base-2], h3 = gh[base-3];
    unsigned int sum = h0 + h1 + h2 + h3;
    unsigned int v = sum;
    #pragma unroll
    for (int off = 1; off < 32; off <<= 1) {
        unsigned int u = __shfl_up_sync(0xffffffffu, v, off);
        if (lane >= off) v += u;
    }
    if (lane == 31) wsum[wrp] = v;
    __syncthreads();
    if (wrp == 0) {
        unsigned int w = wsum[lane];
        #pragma unroll
        for (int off = 1; off < 32; off <<= 1) {
            unsigned int u = __shfl_up_sync(0xffffffffu, w, off);
            if (lane >= off) w += u;
        }
        wsum[lane] = w;
    }
    __syncthreads();
    unsigned int incl = v + (wrp ? wsum[wrp-1] : 0u);
    unsigned int excl = incl - sum;
    if (excl < TOPK && TOPK <= incl) {
        unsigned int c = excl;
        if (c + h0 >= TOPK)      { g_bstar[n] = base;     g_kRem[n] = (int)(TOPK - c); }
        else { c += h0;
        if (c + h1 >= TOPK)      { g_bstar[n] = base - 1; g_kRem[n] = (int)(TOPK - c); }
        else { c += h1;
        if (c + h2 >= TOPK)      { g_bstar[n] = base - 2; g_kRem[n] = (int)(TOPK - c); }
        else { c += h2;            g_bstar[n] = base - 3; g_kRem[n] = (int)(TOPK - c); } } }
    }
    gh[base] = 0; gh[base-1] = 0; gh[base-2] = 0; gh[base-3] = 0;
    if (t == 0) { g_selCount[n] = 0; g_candCount[n] = 0; }
}

// ---------------- compact (many blocks): winners -> g_idx, bucket ties -> 38-bit candidates ----------------
__global__ void compact_kernel(int HW) {
    int n = blockIdx.y;
    int bstar = g_bstar[n];
    const unsigned int* keys = g_keys + n*KEYSTRIDE;
    unsigned long long* cand = g_cand + (size_t)n*KEYSTRIDE;
    int stride = gridDim.x*blockDim.x;
    for (int i = blockIdx.x*blockDim.x + threadIdx.x; i < HW; i += stride) {
        unsigned int key = keys[i];
        int b = (int)(key >> 20);
        if (b > bstar) {
            int p = atomicAdd(&g_selCount[n], 1);
            g_idx[n*PPB + p] = i;
        } else if (b == bstar) {
            int p = atomicAdd(&g_candCount[n], 1);
            cand[p] = (((unsigned long long)(key & 0xFFFFFu)) << 18) | (unsigned int)((~i) & 0x3FFFF);
        }
    }
}

// ---------------- exact select among candidates: 4x10-bit radix (NB blocks) ----------------
__global__ void candsel_kernel() {
    int n = blockIdx.x, t = threadIdx.x;   // 1024
    int lane = t & 31, wrp = t >> 5;
    __shared__ unsigned int hist[1024];
    __shared__ unsigned int wsum[32];
    __shared__ int sh_d;
    __shared__ unsigned int sh_sub;
    int m = g_candCount[n];
    unsigned int need = (unsigned int)g_kRem[n];
    unsigned long long* cand = g_cand + (size_t)n*KEYSTRIDE;
    unsigned long long prefix = 0, pmask = 0;
    if (m > (int)need) {
        #pragma unroll
        for (int pass = 0; pass < 4; pass++) {
            int shift = 30 - 10*pass;
            hist[t] = 0;
            __syncthreads();
            for (int i = t; i < m; i += 1024) {
                unsigned long long c = cand[i];
                if ((c & pmask) == prefix)
                    atomicAdd(&hist[(unsigned int)(c >> shift) & 1023u], 1u);
            }
            __syncthreads();
            unsigned int val = hist[1023 - t];
            unsigned int v = val;
            #pragma unroll
            for (int off = 1; off < 32; off <<= 1) {
                unsigned int u = __shfl_up_sync(0xffffffffu, v, off);
                if (lane >= off) v += u;
            }
            if (lane == 31) wsum[wrp] = v;
            __syncthreads();
            if (wrp == 0) {
                unsigned int w = wsum[lane];
                #pragma unroll
                for (int off = 1; off < 32; off <<= 1) {
                    unsigned int u = __shfl_up_sync(0xffffffffu, w, off);
                    if (lane >= off) w += u;
                }
                wsum[lane] = w;
            }
            __syncthreads();
            unsigned int incl = v + (wrp ? wsum[wrp-1] : 0u);
            unsigned int excl = incl - val;
            if (excl < need && need <= incl) { sh_d = 1023 - t; sh_sub = excl; }
            __syncthreads();
            need -= sh_sub;
            prefix |= ((unsigned long long)(unsigned int)sh_d) << shift;
            pmask  |= 1023ull << shift;
            __syncthreads();
        }
    }
    for (int i = t; i < m; i += 1024) {
        unsigned long long c = cand[i];
        if (c >= prefix) {
            int p = atomicAdd(&g_selCount[n], 1);
            g_idx[n*PPB + p] = (int)((~c) & 0x3FFFF);
        }
    }
}

// ---------------- mega MLP: gather + 3 FC layers + head + scatter ----------------
__global__ void __launch_bounds__(256, 2)
mlp_kernel(const float* __restrict__ coarse, const float2* __restrict__ Wd,
           const float* __restrict__ b1, const float* __restrict__ b2, const float* __restrict__ b3,
           const float* __restrict__ wph, const float* __restrict__ bph,
           float* __restrict__ sem, int HW, int logW) {
    extern __shared__ float sm[];
    float* Xs  = sm;                      // [132][132] activations/coarse/pad
    float* Wsm = sm + FCK*XS_STRIDE;      // 2*1536 float2 (also gather tile scratch)
    __shared__ int   sx0[128], sy0[128];
    __shared__ float sw0[128], sw1[128], sw2[128], sw3[128], spx[128], spy[128];

    int tid = threadIdx.x, lane = tid & 31, wrp = tid >> 5;
    int pBase = blockIdx.x * 128;
    int n = pBase >> 13;

    // ---- point params ----
    if (tid < 128) {
        int id = g_idx[pBase + tid];
        int W = 1 << logW;
        float inv = 1.f / (float)W;
        float px = ((float)(id & (W-1)) + 0.5f) * inv;
        float py = ((float)(id >> logW) + 0.5f) * inv;
        spx[tid] = px; spy[tid] = py;
        float fx = px * 256.f - 0.5f, fy = py * 256.f - 0.5f;
        float fx0 = floorf(fx), fy0 = floorf(fy);
        float wx1 = fx - fx0, wy1 = fy - fy0;
        sx0[tid] = (int)fx0; sy0[tid] = (int)fy0;
        sw0[tid] = (1.f-wx1)*(1.f-wy1);
        sw1[tid] = wx1*(1.f-wy1);
        sw2[tid] = (1.f-wx1)*wy1;
        sw3[tid] = wx1*wy1;
    }
    __syncthreads();

    // ---- gather into Xs via tile scratch (4 sub-rounds of 32 points) ----
    const float* fbase = g_featT + (size_t)n*FH*FH*NIN;
    float* tile = Wsm;                    // [131][33]
    int off = lane << 2;
    for (int s = 0; s < 4; s++) {
        #pragma unroll
        for (int it = 0; it < 4; it++) {
            int j = wrp + it*8;
            int jg = s*32 + j;
            int x0 = sx0[jg], y0 = sy0[jg];
            bool xv0 = (x0 >= 0), xv1 = (x0+1 < FH), yv0 = (y0 >= 0), yv1 = (y0+1 < FH);
            float a0 = 0.f, a1 = 0.f, a2 = 0.f, a3 = 0.f;
            if (xv0 && yv0) { float w = sw0[jg]; float4 v = *(const float4*)(fbase + (size_t)((y0  )*FH + x0  )*NIN + off);
                              a0 += w*v.x; a1 += w*v.y; a2 += w*v.z; a3 += w*v.w; }
            if (xv1 && yv0) { float w = sw1[jg]; float4 v = *(const float4*)(fbase + (size_t)((y0  )*FH + x0+1)*NIN + off);
                              a0 += w*v.x; a1 += w*v.y; a2 += w*v.z; a3 += w*v.w; }
            if (xv0 && yv1) { float w = sw2[jg]; float4 v = *(const float4*)(fbase + (size_t)((y0+1)*FH + x0  )*NIN + off);
                              a0 += w*v.x; a1 += w*v.y; a2 += w*v.z; a3 += w*v.w; }
            if (xv1 && yv1) { float w = sw3[jg]; float4 v = *(const float4*)(fbase + (size_t)((y0+1)*FH + x0+1)*NIN + off);
                              a0 += w*v.x; a1 += w*v.y; a2 += w*v.z; a3 += w*v.w; }
            tile[(off+0)*33 + j] = a0; tile[(off+1)*33 + j] = a1;
            tile[(off+2)*33 + j] = a2; tile[(off+3)*33 + j] = a3;
        }
        if (tid < 96) {
            int j = tid / 3, cc = tid - (tid/3)*3;
            int jg = s*32 + j;
            float cx = spx[jg]*128.f - 0.5f, cy = spy[jg]*128.f - 0.5f;
            float cx0f = floorf(cx), cy0f = floorf(cy);
            int x0 = (int)cx0f, y0 = (int)cy0f;
            float wx1 = cx - cx0f, wy1 = cy - cy0f;
            const float* p = coarse + (size_t)(n*NCLS + cc)*CH*CH;
            float acc = 0.f;
            if (x0 >= 0   && y0 >= 0  ) acc += (1.f-wx1)*(1.f-wy1)*p[y0*CH + x0];
            if (x0+1 < CH && y0 >= 0  ) acc += wx1*(1.f-wy1)*p[y0*CH + x0+1];
            if (x0 >= 0   && y0+1 < CH) acc += (1.f-wx1)*wy1*p[(y0+1)*CH + x0];
            if (x0+1 < CH && y0+1 < CH) acc += wx1*wy1*p[(y0+1)*CH + x0+1];
            tile[(NIN+cc)*33 + j] = acc;
        }
        __syncthreads();
        for (int idx = tid; idx < 132*32; idx += 256) {
            int r = idx >> 5, j = idx & 31;
            float v = (r < KIN) ? tile[r*33 + j] : 0.f;
            Xs[r*XS_STRIDE + s*32 + j] = v;
        }
        __syncthreads();
    }

    // ---- stage W chunk 0 ----
    {
        const float4* wg = (const float4*)Wd;
        float4* wd = (float4*)Wsm;
        wd[tid] = wg[tid]; wd[tid+256] = wg[tid+256]; wd[tid+512] = wg[tid+512];
    }
    __syncthreads();

    int o0 = (tid >> 4) << 3;
    int p0 = (tid & 15) << 3;
    const float* Bl0 = b1;
    int flat = 0;
    for (int l = 0; l < 3; l++) {
        const float* Bp = (l == 0) ? b1 : ((l == 1) ? b2 : b3);
        unsigned long long acc[8][4];
        #pragma unroll
        for (int o = 0; o < 8; o++)
            #pragma unroll
            for (int j = 0; j < 4; j++) acc[o][j] = 0ull;

        for (int cch = 0; cch < NCH; cch++) {
            int cur = flat & 1;
            bool hasNext = (flat < 32);
            float4 wpre0, wpre1, wpre2;
            if (hasNext) {
                const float4* wg = (const float4*)(Wd + (size_t)(flat+1)*WCHUNK);
                wpre0 = wg[tid]; wpre1 = wg[tid+256]; wpre2 = wg[tid+512];
            }
            float2* Wc = (float2*)Wsm + cur*WCHUNK;
            const float* Xc = Xs + cch*KCH*XS_STRIDE;
            #pragma unroll
            for (int kk = 0; kk < KCH; kk++) {
                const ulonglong2* wrow = (const ulonglong2*)(Wc + kk*128 + o0);
                const ulonglong2* xrow = (const ulonglong2*)(Xc + kk*XS_STRIDE + p0);
                ulonglong2 w01 = wrow[0], w23 = wrow[1], w45 = wrow[2], w67 = wrow[3];
                ulonglong2 xA = xrow[0], xB = xrow[1];
                unsigned long long w[8] = {w01.x, w01.y, w23.x, w23.y, w45.x, w45.y, w67.x, w67.y};
                unsigned long long x[4] = {xA.x, xA.y, xB.x, xB.y};
                #pragma unroll
                for (int o = 0; o < 8; o++)
                    #pragma unroll
                    for (int j = 0; j < 4; j++)
                        acc[o][j] = ffma2(w[o], x[j], acc[o][j]);
            }
            if (hasNext) {
                __syncthreads();
                float4* wd = (float4*)((float2*)Wsm + (cur^1)*WCHUNK);
                wd[tid] = wpre0; wd[tid+256] = wpre1; wd[tid+512] = wpre2;
                __syncthreads();
            }
            flat++;
        }
        if (l == 2) __syncthreads();   // last chunk had no prefetch sync
        // writeback relu outputs into Xs rows 0..127
        #pragma unroll
        for (int o = 0; o < 8; o++) {
            float bo = __ldg(&Bp[o0 + o]);
            float r[8];
            #pragma unroll
            for (int j = 0; j < 4; j++) unpack2(acc[o][j], r[2*j], r[2*j+1]);
            float4 A, Bv;
            A.x  = fmaxf(r[0]+bo, 0.f); A.y  = fmaxf(r[1]+bo, 0.f);
            A.z  = fmaxf(r[2]+bo, 0.f); A.w  = fmaxf(r[3]+bo, 0.f);
            Bv.x = fmaxf(r[4]+bo, 0.f); Bv.y = fmaxf(r[5]+bo, 0.f);
            Bv.z = fmaxf(r[6]+bo, 0.f); Bv.w = fmaxf(r[7]+bo, 0.f);
            *(float4*)(Xs + (o0+o)*XS_STRIDE + p0)     = A;
            *(float4*)(Xs + (o0+o)*XS_STRIDE + p0 + 4) = Bv;
        }
        __syncthreads();
    }
    (void)Bl0;

    // ---- head (131 -> 3) + scatter ----
    if (tid < 128) {
        int gp = pBase + tid;
        float a0 = 0.f, a1 = 0.f, a2 = 0.f;
        for (int k = 0; k < KIN; k++) {
            float xv = Xs[k*XS_STRIDE + tid];
            a0 += __ldg(&wph[k])*xv;
            a1 += __ldg(&wph[KIN + k])*xv;
            a2 += __ldg(&wph[2*KIN + k])*xv;
        }
        int id = g_idx[gp];
        sem[(size_t)(n*NCLS + 0)*HW + id] = a0 + __ldg(&bph[0]);
        sem[(size_t)(n*NCLS + 1)*HW + id] = a1 + __ldg(&bph[1]);
        sem[(size_t)(n*NCLS + 2)*HW + id] = a2 + __ldg(&bph[2]);
    }
}

// ---------------- launch ----------------
extern "C" void kernel_launch(void* const* d_in, const int* in_sizes, int n_in,
                              void* d_out, int out_size) {
    const float* coarse = (const float*)d_in[0];
    const float* feat   = (const float*)d_in[1];
    const float* w1 = (const float*)d_in[2];
    const float* b1 = (const float*)d_in[3];
    const float* w2 = (const float*)d_in[4];
    const float* b2 = (const float*)d_in[5];
    const float* w3 = (const float*)d_in[6];
    const float* b3 = (const float*)d_in[7];
    const float* wp = (const float*)d_in[8];
    const float* bp = (const float*)d_in[9];
    float* out = (float*)d_out;

    float* sem256;
    float2* Wd;
    cudaGetSymbolAddress((void**)&sem256, g_sem256);
    cudaGetSymbolAddress((void**)&Wd, g_Wd);

    const int MLPSMEM = (FCK*XS_STRIDE + 2*WCHUNK*2) * 4;   // 69,696 + 24,576 = 94,272 B
    cudaFuncSetAttribute(mlp_kernel, cudaFuncAttributeMaxDynamicSharedMemorySize, MLPSMEM);

    prep_kernel<<<256, 256>>>(w1, w2, w3);
    transpose_kernel<<<dim3(2048, 4, 4), dim3(32, 8)>>>(feat);

    for (int step = 0; step < 2; step++) {
        int logW = (step == 0) ? 8 : 9;
        int HW   = 1 << (2*logW);
        const float* semIn = (step == 0) ? coarse : sem256;
        float* semOut      = (step == 0) ? sem256 : out;

        upsample_unc_hist<<<dim3(HW/1024, NB), 256>>>(semIn, semOut, logW);
        resolve_kernel<<<NB, 1024>>>();
        compact_kernel<<<dim3(HW/2048, NB), 256>>>(HW);
        candsel_kernel<<<NB, 1024>>>();

        mlp_kernel<<<PTOT/128, 256, MLPSMEM>>>(coarse, Wd, b1, b2, b3, wp, bp, semOut, HW, logW);
    }
}